// round 14
// baseline (speedup 1.0000x reference)
#include <cuda_runtime.h>
#include <cuda_fp16.h>
#include <cstdint>

#define Sc 2048
#define Ec 1024
#define Hc 16
#define HDc 64
#define Mrows 8192

// Scratch (fp16). q/k: [bh][s][d]; v: [bh][d][s]; attn: [b][s][e]
__device__ __half g_q[(size_t)Mrows * Ec];
__device__ __half g_k[(size_t)Mrows * Ec];
__device__ __half g_v[(size_t)Mrows * Ec];
__device__ __half g_attn[(size_t)Mrows * Ec];
// fp16 pre-converted weights
__device__ __half g_wq[(size_t)Ec * Ec];
__device__ __half g_wk[(size_t)Ec * Ec];
__device__ __half g_wv[(size_t)Ec * Ec];
__device__ __half g_wo[(size_t)Ec * Ec];

__device__ __forceinline__ uint32_t h2(float x, float y) {
    __half2 h = __halves2half2(__float2half_rn(x), __float2half_rn(y));
    return *reinterpret_cast<uint32_t*>(&h);
}

__device__ __forceinline__ void mma16(float c[4], const uint32_t a[4],
                                      const uint32_t b[2]) {
    asm volatile(
        "mma.sync.aligned.m16n8k16.row.col.f32.f16.f16.f32 "
        "{%0,%1,%2,%3}, {%4,%5,%6,%7}, {%8,%9}, {%0,%1,%2,%3};\n"
        : "+f"(c[0]), "+f"(c[1]), "+f"(c[2]), "+f"(c[3])
        : "r"(a[0]), "r"(a[1]), "r"(a[2]), "r"(a[3]), "r"(b[0]), "r"(b[1]));
}

__device__ __forceinline__ void ldsm4(uint32_t r[4], uint32_t a) {
    asm volatile(
        "ldmatrix.sync.aligned.m8n8.x4.shared.b16 {%0,%1,%2,%3}, [%4];"
        : "=r"(r[0]), "=r"(r[1]), "=r"(r[2]), "=r"(r[3])
        : "r"(a));
}

__device__ __forceinline__ void cp16(uint32_t s, const void* g) {
    asm volatile("cp.async.cg.shared.global [%0], [%1], 16;" ::"r"(s), "l"(g)
                 : "memory");
}
#define CP_COMMIT asm volatile("cp.async.commit_group;" ::: "memory")
#define CP_WAIT(n) asm volatile("cp.async.wait_group %0;" ::"n"(n) : "memory")
#define STS128(a, u0, u1, u2, u3)                                  \
    asm volatile("st.shared.v4.b32 [%0], {%1,%2,%3,%4};" ::"r"(a), \
                 "r"(u0), "r"(u1), "r"(u2), "r"(u3))

// ---------------------------------------------------------------------------
// fp16 pre-convert for the 4 weight matrices in one launch
// ---------------------------------------------------------------------------
__global__ void conv_w(const float4* __restrict__ s0, uint2* __restrict__ d0,
                       const float4* __restrict__ s1, uint2* __restrict__ d1,
                       const float4* __restrict__ s2, uint2* __restrict__ d2,
                       const float4* __restrict__ s3, uint2* __restrict__ d3) {
    const float4* src;
    uint2* dst;
    switch (blockIdx.y) {
        case 0: src = s0; dst = d0; break;
        case 1: src = s1; dst = d1; break;
        case 2: src = s2; dst = d2; break;
        default: src = s3; dst = d3; break;
    }
    const int n4 = Ec * Ec / 4;
    int i = blockIdx.x * blockDim.x + threadIdx.x;
    const int stride = gridDim.x * blockDim.x;
    for (; i < n4; i += stride) {
        float4 v = src[i];
        dst[i] = make_uint2(h2(v.x, v.y), h2(v.z, v.w));
    }
}

// ---------------------------------------------------------------------------
// fp16 GEMM: C[M,1024] = A @ W^T + bias.  W fp16 via cp.async.
// CTA 128x256, warp tile 64x64 (2m x 4n warps), BK=32, 32 chunks.
// THREE-stage ring, stage-ahead 2, ONE sync per chunk:
//   iter c: CP_WAIT(1) -> sync -> stage chunk c+2 into slot (c+2)%3
//   (== slot (c-1)%3, readers passed this sync) -> compute slot c%3.
// SMEM row = 32 halves (64B) + 16B pad = 80B.
// Stage: A 128x80 + W 256x80 = 30720B; 3 stages = 92160B. 1 CTA/SM.
// CVTA=1: A raw fp32, register-prefetched LDG->cvt->STS staging.
// EPI: 0 fp32 [M,N]; 1 Q (x0.125, fp16, [bh][s][d]); 2 K (fp16, [bh][s][d]);
//      3 V (fp16, transposed [bh][d][s]).
// ---------------------------------------------------------------------------
template <int EPI, int CVTA>
__global__ void __launch_bounds__(256, 1)
    gemm_tc(const void* __restrict__ Av, const __half* __restrict__ W,
            const float* __restrict__ bias, void* __restrict__ Cv) {
    extern __shared__ uint32_t gsm[];
    const uint32_t smb = (uint32_t)__cvta_generic_to_shared(gsm);

    const int tid = threadIdx.x, lane = tid & 31, warp = tid >> 5;
    const int wm = warp >> 2, wn = warp & 3;  // 2(m) x 4(n), 64x64 each
    const int gr = lane >> 2, gc = lane & 3;
    const int r0 = blockIdx.x << 7, c0 = blockIdx.y << 8;

    const int lm15 = lane & 15, l7 = lane & 7, l16 = (lane >> 4) & 1;
    const uint32_t colA = ((lane >> 4) & 1) << 4;
    const uint32_t colB = ((lane >> 3) & 1) << 4;
    const uint32_t a_lane = (uint32_t)(wm * 64 + lm15) * 80 + colA;
    const uint32_t b_lane = (uint32_t)(wn * 64 + l16 * 8 + l7) * 80 + colB;

    // A staging: 2 threads per row, 32B (16 halves) each
    const int srow = tid >> 1, sseg = (tid & 1) << 4;
    const uint32_t dstA = smb + (uint32_t)srow * 80 + sseg * 2;
    const float* Apf = (const float*)Av + (size_t)(r0 + srow) * Ec + sseg;
    const __half* Aph = (const __half*)Av + (size_t)(r0 + srow) * Ec + sseg;
    // W staging: 1 thread per row (256 rows), 64B each
    const uint32_t dstW = smb + 10240 + (uint32_t)tid * 80;
    const __half* Wp = W + (size_t)(c0 + tid) * Ec;

    float acc[4][8][4];
#pragma unroll
    for (int mi = 0; mi < 4; mi++)
#pragma unroll
        for (int ni = 0; ni < 8; ni++)
#pragma unroll
            for (int j = 0; j < 4; j++) acc[mi][ni][j] = 0.f;

    float4 pa[4];
    // prologue: stage chunks 0,1 into slots 0,1
#pragma unroll
    for (int ch = 0; ch < 2; ch++) {
        const uint32_t st = (uint32_t)ch * 30720;
        if (CVTA) {
#pragma unroll
            for (int u = 0; u < 4; u++)
                pa[u] = *(const float4*)(Apf + (ch << 5) + (u << 2));
            STS128(dstA + st, h2(pa[0].x, pa[0].y), h2(pa[0].z, pa[0].w),
                   h2(pa[1].x, pa[1].y), h2(pa[1].z, pa[1].w));
            STS128(dstA + st + 16, h2(pa[2].x, pa[2].y), h2(pa[2].z, pa[2].w),
                   h2(pa[3].x, pa[3].y), h2(pa[3].z, pa[3].w));
        } else {
            cp16(dstA + st, Aph + (ch << 5));
            cp16(dstA + st + 16, Aph + (ch << 5) + 8);
        }
#pragma unroll
        for (int u = 0; u < 4; u++)
            cp16(dstW + st + u * 16, Wp + (ch << 5) + (u << 3));
        CP_COMMIT;
    }
    if (CVTA) {  // prefetch chunk 2
#pragma unroll
        for (int u = 0; u < 4; u++)
            pa[u] = *(const float4*)(Apf + (2 << 5) + (u << 2));
    }

    for (int c = 0; c < 32; c++) {
        if (c < 31) { CP_WAIT(1); } else { CP_WAIT(0); }
        __syncthreads();  // chunk c visible; chunk c-1 readers done

        // stage chunk c+2 into slot (c+2)%3
        if (c + 2 < 32) {
            const uint32_t st = (uint32_t)((c + 2) % 3) * 30720;
            const int nch = c + 2;
            if (CVTA) {  // pa holds chunk c+2
                STS128(dstA + st, h2(pa[0].x, pa[0].y), h2(pa[0].z, pa[0].w),
                       h2(pa[1].x, pa[1].y), h2(pa[1].z, pa[1].w));
                STS128(dstA + st + 16, h2(pa[2].x, pa[2].y),
                       h2(pa[2].z, pa[2].w), h2(pa[3].x, pa[3].y),
                       h2(pa[3].z, pa[3].w));
            } else {
                cp16(dstA + st, Aph + (nch << 5));
                cp16(dstA + st + 16, Aph + (nch << 5) + 8);
            }
#pragma unroll
            for (int u = 0; u < 4; u++)
                cp16(dstW + st + u * 16, Wp + (nch << 5) + (u << 3));
            CP_COMMIT;
            if (CVTA && c + 3 < 32) {
#pragma unroll
                for (int u = 0; u < 4; u++)
                    pa[u] = *(const float4*)(Apf + ((c + 3) << 5) + (u << 2));
            }
        }

        const uint32_t asb = smb + (uint32_t)(c % 3) * 30720;
        const uint32_t wsb = asb + 10240;
#pragma unroll
        for (int ki = 0; ki < 2; ki++) {
            uint32_t af[4][4];
#pragma unroll
            for (int mi = 0; mi < 4; mi++)
                ldsm4(af[mi], asb + a_lane + mi * 1280 + ki * 32);
#pragma unroll
            for (int t = 0; t < 4; t++) {
                uint32_t bq[4];
                ldsm4(bq, wsb + b_lane + t * 1280 + ki * 32);
#pragma unroll
                for (int mi = 0; mi < 4; mi++) {
                    mma16(acc[mi][2 * t], af[mi], bq);
                    mma16(acc[mi][2 * t + 1], af[mi], bq + 2);
                }
            }
        }
    }

    // Epilogue
#pragma unroll
    for (int ni = 0; ni < 8; ni++) {
        const int col = c0 + (wn << 6) + (ni << 3) + (gc << 1);
        const float2 b2 = *(const float2*)&bias[col];
#pragma unroll
        for (int mi = 0; mi < 4; mi++) {
            const int row = r0 + (wm << 6) + (mi << 4) + gr;
            float v00 = acc[mi][ni][0] + b2.x, v01 = acc[mi][ni][1] + b2.y;
            float v10 = acc[mi][ni][2] + b2.x, v11 = acc[mi][ni][3] + b2.y;
            if (EPI == 0) {
                float* C = (float*)Cv;
                *(float2*)&C[(size_t)row * Ec + col] = make_float2(v00, v01);
                *(float2*)&C[(size_t)(row + 8) * Ec + col] =
                    make_float2(v10, v11);
            } else {
                if (EPI == 1) {
                    v00 *= 0.125f; v01 *= 0.125f; v10 *= 0.125f; v11 *= 0.125f;
                }
                const int b = row >> 11, s = row & (Sc - 1);
                const int h = col >> 6, d = col & (HDc - 1);
                const int bh = (b << 4) + h;
                __half* C = (__half*)Cv;
                if (EPI == 3) {
                    // [bh][d][s]
                    __half* base0 = C + (((size_t)(bh << 6) + d) << 11) + s;
                    __half* base1 = base0 + Sc;  // d+1
                    base0[0] = __float2half_rn(v00);
                    base0[8] = __float2half_rn(v10);
                    base1[0] = __float2half_rn(v01);
                    base1[8] = __float2half_rn(v11);
                } else {
                    // [bh][s][d]
                    __half* base = C + ((size_t)bh << 17) + (s << 6) + d;
                    *(uint32_t*)base = h2(v00, v01);
                    *(uint32_t*)(base + (8 << 6)) = h2(v10, v11);
                }
            }
        }
    }
}

// ---------------------------------------------------------------------------
// Flash attention (byte-identical to R13): fp16 mma, fp32 softmax/acc.
// THREE-stage KV ring, one sync per tile.
// SMEM bytes: KV slots [0,18432) [18432,36864) [36864,55296),
//             Ps/Qstage [55296,73728). Rows: 64 halves + 16B pad = 144B.
// ---------------------------------------------------------------------------
__global__ void __launch_bounds__(256, 2)
    attn_tc(const __half* __restrict__ Q, const __half* __restrict__ K,
            const __half* __restrict__ V, __half* __restrict__ O) {
    extern __shared__ uint32_t asm_sm[];
    const uint32_t smb = (uint32_t)__cvta_generic_to_shared(asm_sm);
    const uint32_t PsB = smb + 55296;
    char* PsG = (char*)asm_sm + 55296;

    const int tid = threadIdx.x, lane = tid & 31, warp = tid >> 5;
    const int gr = lane >> 2, gc = lane & 3;
    const int qi = gridDim.x - 1 - blockIdx.x;  // heavy tiles first
    const int bh = blockIdx.y;
    const int q0 = qi << 7;
    const int rb = warp << 4;

    const int lm15 = lane & 15, l7 = lane & 7, l16 = (lane >> 4) & 1;
    const uint32_t colA = ((lane >> 4) & 1) << 4;
    const uint32_t colB = ((lane >> 3) & 1) << 4;
    const uint32_t p_lane = (uint32_t)(rb + lm15) * 144 + colA;
    const uint32_t kb_lane = (uint32_t)(l16 * 8 + l7) * 144 + colB;

    const __half* qb = Q + ((size_t)bh << 17);
    const __half* kb = K + ((size_t)bh << 17);
    const __half* vb = V + ((size_t)bh << 17);

    const int krow = tid >> 2, ku = (tid & 3) * 2;
    auto stage_kv = [&](int kt, uint32_t slot) {
        const int t0 = kt << 6;
        const uint32_t st = slot * 18432;
#pragma unroll
        for (int u = 0; u < 2; u++) {
            cp16(smb + st + (uint32_t)krow * 144 + (ku + u) * 16,
                 kb + (size_t)(t0 + krow) * HDc + (ku + u) * 8);
            cp16(smb + st + 9216 + (uint32_t)krow * 144 + (ku + u) * 16,
                 vb + (size_t)krow * Sc + t0 + (ku + u) * 8);
        }
        CP_COMMIT;
    };

    const int ktiles = (qi << 1) + 2;

    stage_kv(0, 0);
    const int qrow = tid >> 1, qseg = (tid & 1) * 4;
#pragma unroll
    for (int u = 0; u < 4; u++)
        cp16(PsB + (uint32_t)qrow * 144 + (qseg + u) * 16,
             qb + (size_t)(q0 + qrow) * HDc + (qseg + u) * 8);
    CP_COMMIT;
    CP_WAIT(0);
    __syncthreads();
    uint32_t qf[4][4];
#pragma unroll
    for (int ki = 0; ki < 4; ki++) ldsm4(qf[ki], PsB + p_lane + ki * 32);
    __syncthreads();
    if (ktiles > 1) stage_kv(1, 1);

    float m0 = -1e30f, m1 = -1e30f, l0 = 0.f, l1 = 0.f;
    float o[8][4];
#pragma unroll
    for (int ni = 0; ni < 8; ni++)
#pragma unroll
        for (int j = 0; j < 4; j++) o[ni][j] = 0.f;

    for (int kt = 0; kt < ktiles; kt++) {
        if (kt + 1 < ktiles) { CP_WAIT(1); } else { CP_WAIT(0); }
        __syncthreads();

        if (kt + 2 < ktiles) stage_kv(kt + 2, (uint32_t)((kt + 2) % 3));

        const uint32_t ksb = smb + (uint32_t)(kt % 3) * 18432;
        const uint32_t vsb = ksb + 9216;

        float s[8][4];
#pragma unroll
        for (int ni = 0; ni < 8; ni++)
#pragma unroll
            for (int j = 0; j < 4; j++) s[ni][j] = 0.f;
#pragma unroll
        for (int ki = 0; ki < 4; ki++) {
#pragma unroll
            for (int t = 0; t < 4; t++) {
                uint32_t bq[4];
                ldsm4(bq, ksb + kb_lane + t * 2304 + ki * 32);
                mma16(s[2 * t], qf[ki], bq);
                mma16(s[2 * t + 1], qf[ki], bq + 2);
            }
        }

        const int k0 = kt << 6;
        if (k0 + 63 > q0) {
            const int row0 = q0 + rb + gr, row1 = row0 + 8;
#pragma unroll
            for (int ni = 0; ni < 8; ni++) {
                const int cg = k0 + (ni << 3) + (gc << 1);
                if (cg > row0) s[ni][0] = -1e30f;
                if (cg + 1 > row0) s[ni][1] = -1e30f;
                if (cg > row1) s[ni][2] = -1e30f;
                if (cg + 1 > row1) s[ni][3] = -1e30f;
            }
        }

        float mx0 = -1e30f, mx1 = -1e30f;
#pragma unroll
        for (int ni = 0; ni < 8; ni++) {
            mx0 = fmaxf(mx0, fmaxf(s[ni][0], s[ni][1]));
            mx1 = fmaxf(mx1, fmaxf(s[ni][2], s[ni][3]));
        }
        mx0 = fmaxf(mx0, __shfl_xor_sync(0xffffffffu, mx0, 1));
        mx0 = fmaxf(mx0, __shfl_xor_sync(0xffffffffu, mx0, 2));
        mx1 = fmaxf(mx1, __shfl_xor_sync(0xffffffffu, mx1, 1));
        mx1 = fmaxf(mx1, __shfl_xor_sync(0xffffffffu, mx1, 2));

        const float mn0 = fmaxf(m0, mx0), mn1 = fmaxf(m1, mx1);
        const float cor0 = __expf(m0 - mn0), cor1 = __expf(m1 - mn1);
        float sum0 = 0.f, sum1 = 0.f;
#pragma unroll
        for (int ni = 0; ni < 8; ni++) {
            s[ni][0] = __expf(s[ni][0] - mn0);
            s[ni][1] = __expf(s[ni][1] - mn0);
            s[ni][2] = __expf(s[ni][2] - mn1);
            s[ni][3] = __expf(s[ni][3] - mn1);
            sum0 += s[ni][0] + s[ni][1];
            sum1 += s[ni][2] + s[ni][3];
        }
        sum0 += __shfl_xor_sync(0xffffffffu, sum0, 1);
        sum0 += __shfl_xor_sync(0xffffffffu, sum0, 2);
        sum1 += __shfl_xor_sync(0xffffffffu, sum1, 1);
        sum1 += __shfl_xor_sync(0xffffffffu, sum1, 2);

        l0 = l0 * cor0 + sum0;
        l1 = l1 * cor1 + sum1;
        m0 = mn0;
        m1 = mn1;
#pragma unroll
        for (int ni = 0; ni < 8; ni++) {
            o[ni][0] *= cor0;
            o[ni][1] *= cor0;
            o[ni][2] *= cor1;
            o[ni][3] *= cor1;
        }

#pragma unroll
        for (int ni = 0; ni < 8; ni++) {
            char* a0 = PsG + (uint32_t)(rb + gr) * 144 +
                       ((ni << 3) + (gc << 1)) * 2;
            *(uint32_t*)a0 = h2(s[ni][0], s[ni][1]);
            *(uint32_t*)(a0 + 1152) = h2(s[ni][2], s[ni][3]);
        }
        __syncwarp();

#pragma unroll
        for (int ki = 0; ki < 4; ki++) {
            uint32_t pf[4];
            ldsm4(pf, PsB + p_lane + ki * 32);
#pragma unroll
            for (int t = 0; t < 4; t++) {
                uint32_t bq[4];
                ldsm4(bq, vsb + kb_lane + t * 2304 + ki * 32);
                mma16(o[2 * t], pf, bq);
                mma16(o[2 * t + 1], pf, bq + 2);
            }
        }
    }

    const int b = bh >> 4, h = bh & 15;
    const float i0 = 1.f / l0, i1 = 1.f / l1;
    __half* ob = O + ((size_t)b * Sc) * Ec + h * HDc;
    const int row0 = q0 + rb + gr;
#pragma unroll
    for (int ni = 0; ni < 8; ni++) {
        const int d = (ni << 3) + (gc << 1);
        *(uint32_t*)(ob + (size_t)row0 * Ec + d) =
            h2(o[ni][0] * i0, o[ni][1] * i0);
        *(uint32_t*)(ob + (size_t)(row0 + 8) * Ec + d) =
            h2(o[ni][2] * i1, o[ni][3] * i1);
    }
}

// ---------------------------------------------------------------------------
// Inputs: 0 values, 1 keys, 2 queries, 3 mask, 4 Wv, 5 bv, 6 Wk, 7 bk,
//         8 Wq, 9 bq, 10 Wo, 11 bo
// ---------------------------------------------------------------------------
extern "C" void kernel_launch(void* const* d_in, const int* in_sizes, int n_in,
                              void* d_out, int out_size) {
    const float* values = (const float*)d_in[0];
    const float* keys = (const float*)d_in[1];
    const float* queries = (const float*)d_in[2];
    const float* Wv = (const float*)d_in[4];
    const float* bv = (const float*)d_in[5];
    const float* Wk = (const float*)d_in[6];
    const float* bk = (const float*)d_in[7];
    const float* Wq = (const float*)d_in[8];
    const float* bq = (const float*)d_in[9];
    const float* Wo = (const float*)d_in[10];
    const float* bo = (const float*)d_in[11];
    float* out = (float*)d_out;

    __half *qb_, *kb_, *vb_, *ab_, *wq_, *wk_, *wv_, *wo_;
    cudaGetSymbolAddress((void**)&qb_, g_q);
    cudaGetSymbolAddress((void**)&kb_, g_k);
    cudaGetSymbolAddress((void**)&vb_, g_v);
    cudaGetSymbolAddress((void**)&ab_, g_attn);
    cudaGetSymbolAddress((void**)&wq_, g_wq);
    cudaGetSymbolAddress((void**)&wk_, g_wk);
    cudaGetSymbolAddress((void**)&wv_, g_wv);
    cudaGetSymbolAddress((void**)&wo_, g_wo);

    const int gemm_smem = 92160;  // 3 stages x 30720
    const int attn_smem = 73728;  // 3 KV slots + Ps
    cudaFuncSetAttribute(gemm_tc<0, 0>, cudaFuncAttributeMaxDynamicSharedMemorySize, gemm_smem);
    cudaFuncSetAttribute(gemm_tc<1, 1>, cudaFuncAttributeMaxDynamicSharedMemorySize, gemm_smem);
    cudaFuncSetAttribute(gemm_tc<2, 1>, cudaFuncAttributeMaxDynamicSharedMemorySize, gemm_smem);
    cudaFuncSetAttribute(gemm_tc<3, 1>, cudaFuncAttributeMaxDynamicSharedMemorySize, gemm_smem);
    cudaFuncSetAttribute(attn_tc, cudaFuncAttributeMaxDynamicSharedMemorySize, attn_smem);

    dim3 gw(256, 4);
    conv_w<<<gw, 256>>>((const float4*)Wq, (uint2*)wq_, (const float4*)Wk,
                        (uint2*)wk_, (const float4*)Wv, (uint2*)wv_,
                        (const float4*)Wo, (uint2*)wo_);

    dim3 gg(Mrows / 128, Ec / 256);  // (64, 4)
    gemm_tc<1, 1><<<gg, 256, gemm_smem>>>(queries, wq_, bq, qb_);
    gemm_tc<2, 1><<<gg, 256, gemm_smem>>>(keys, wk_, bk, kb_);
    gemm_tc<3, 1><<<gg, 256, gemm_smem>>>(values, wv_, bv, vb_);

    dim3 ga(Sc / 128, 4 * Hc);  // (16, 64)
    attn_tc<<<ga, 256, attn_smem>>>(qb_, kb_, vb_, ab_);

    gemm_tc<0, 0><<<gg, 256, gemm_smem>>>(ab_, wo_, bo, out);
}

// round 15
// speedup vs baseline: 1.1501x; 1.1501x over previous
#include <cuda_runtime.h>
#include <cuda_fp16.h>
#include <cstdint>

#define Sc 2048
#define Ec 1024
#define Hc 16
#define HDc 64
#define Mrows 8192

// Scratch (fp16). q/k: [bh][s][d]; v: [bh][d][s]; attn: [b][s][e]
__device__ __half g_q[(size_t)Mrows * Ec];
__device__ __half g_k[(size_t)Mrows * Ec];
__device__ __half g_v[(size_t)Mrows * Ec];
__device__ __half g_attn[(size_t)Mrows * Ec];
// fp16 pre-converted weights
__device__ __half g_wq[(size_t)Ec * Ec];
__device__ __half g_wk[(size_t)Ec * Ec];
__device__ __half g_wv[(size_t)Ec * Ec];
__device__ __half g_wo[(size_t)Ec * Ec];

__device__ __forceinline__ uint32_t h2(float x, float y) {
    __half2 h = __halves2half2(__float2half_rn(x), __float2half_rn(y));
    return *reinterpret_cast<uint32_t*>(&h);
}

__device__ __forceinline__ void mma16(float c[4], const uint32_t a[4],
                                      const uint32_t b[2]) {
    asm volatile(
        "mma.sync.aligned.m16n8k16.row.col.f32.f16.f16.f32 "
        "{%0,%1,%2,%3}, {%4,%5,%6,%7}, {%8,%9}, {%0,%1,%2,%3};\n"
        : "+f"(c[0]), "+f"(c[1]), "+f"(c[2]), "+f"(c[3])
        : "r"(a[0]), "r"(a[1]), "r"(a[2]), "r"(a[3]), "r"(b[0]), "r"(b[1]));
}

__device__ __forceinline__ void ldsm4(uint32_t r[4], uint32_t a) {
    asm volatile(
        "ldmatrix.sync.aligned.m8n8.x4.shared.b16 {%0,%1,%2,%3}, [%4];"
        : "=r"(r[0]), "=r"(r[1]), "=r"(r[2]), "=r"(r[3])
        : "r"(a));
}

__device__ __forceinline__ void cp16(uint32_t s, const void* g) {
    asm volatile("cp.async.cg.shared.global [%0], [%1], 16;" ::"r"(s), "l"(g)
                 : "memory");
}
#define CP_COMMIT asm volatile("cp.async.commit_group;" ::: "memory")
#define CP_WAIT(n) asm volatile("cp.async.wait_group %0;" ::"n"(n) : "memory")
#define STS128(a, u0, u1, u2, u3)                                  \
    asm volatile("st.shared.v4.b32 [%0], {%1,%2,%3,%4};" ::"r"(a), \
                 "r"(u0), "r"(u1), "r"(u2), "r"(u3))

// ---------------------------------------------------------------------------
// fp16 pre-convert for the 4 weight matrices in one launch
// ---------------------------------------------------------------------------
__global__ void conv_w(const float4* __restrict__ s0, uint2* __restrict__ d0,
                       const float4* __restrict__ s1, uint2* __restrict__ d1,
                       const float4* __restrict__ s2, uint2* __restrict__ d2,
                       const float4* __restrict__ s3, uint2* __restrict__ d3) {
    const float4* src;
    uint2* dst;
    switch (blockIdx.y) {
        case 0: src = s0; dst = d0; break;
        case 1: src = s1; dst = d1; break;
        case 2: src = s2; dst = d2; break;
        default: src = s3; dst = d3; break;
    }
    const int n4 = Ec * Ec / 4;
    int i = blockIdx.x * blockDim.x + threadIdx.x;
    const int stride = gridDim.x * blockDim.x;
    for (; i < n4; i += stride) {
        float4 v = src[i];
        dst[i] = make_uint2(h2(v.x, v.y), h2(v.z, v.w));
    }
}

// ---------------------------------------------------------------------------
// fp16 GEMM: C[M,1024] = A @ W^T + bias.  W fp16 via cp.async.
// CTA = 128 THREADS (4 warps), tile 128x128, warp tile 64x64 (2m x 2n).
// 2 CTAs/SM: per-chunk barriers convoy only half the SM's warps.
// BK=32 (32 chunks), 3-stage ring, stage-ahead 2, one sync per chunk.
// SMEM row = 32 halves (64B) + 16B pad = 80B; stage A+W = 20480B; x3 = 61440B.
// CVTA=1: A raw fp32, 2-pass register-prefetched LDG->cvt->STS staging.
// EPI: 0 fp32 [M,N]; 1 Q (x0.125, fp16, [bh][s][d]); 2 K (fp16, [bh][s][d]);
//      3 V (fp16, transposed [bh][d][s]).
// ---------------------------------------------------------------------------
template <int EPI, int CVTA>
__global__ void __launch_bounds__(128, 2)
    gemm_tc(const void* __restrict__ Av, const __half* __restrict__ W,
            const float* __restrict__ bias, void* __restrict__ Cv) {
    extern __shared__ uint32_t gsm[];
    const uint32_t smb = (uint32_t)__cvta_generic_to_shared(gsm);

    const int tid = threadIdx.x, lane = tid & 31, warp = tid >> 5;
    const int wm = warp >> 1, wn = warp & 1;  // 2(m) x 2(n), 64x64 each
    const int gr = lane >> 2, gc = lane & 3;
    const int r0 = blockIdx.x << 7, c0 = blockIdx.y << 7;

    const int lm15 = lane & 15, l7 = lane & 7, l16 = (lane >> 4) & 1;
    const uint32_t colA = ((lane >> 4) & 1) << 4;
    const uint32_t colB = ((lane >> 3) & 1) << 4;
    const uint32_t a_lane = (uint32_t)(wm * 64 + lm15) * 80 + colA;
    const uint32_t b_lane = (uint32_t)(wn * 64 + l16 * 8 + l7) * 80 + colB;

    // staging: 2 threads per row (64 rows/pass), 32B each, 2 passes
    const int srow = tid >> 1, sseg = (tid & 1) << 4;
    const uint32_t dstA = smb + (uint32_t)srow * 80 + sseg * 2;
    const uint32_t dstW = dstA + 10240;
    const float* Apf = (const float*)Av + (size_t)(r0 + srow) * Ec + sseg;
    const __half* Aph = (const __half*)Av + (size_t)(r0 + srow) * Ec + sseg;
    const __half* Wp = W + (size_t)(c0 + srow) * Ec + sseg;

    float acc[4][8][4];
#pragma unroll
    for (int mi = 0; mi < 4; mi++)
#pragma unroll
        for (int ni = 0; ni < 8; ni++)
#pragma unroll
            for (int j = 0; j < 4; j++) acc[mi][ni][j] = 0.f;

    float4 pa[2][4];  // [pass][4 float4] = 32 floats = chunk slice of A
    // prologue: stage chunks 0,1 into slots 0,1 (direct LDG->STS for CVTA)
#pragma unroll
    for (int ch = 0; ch < 2; ch++) {
        const uint32_t st = (uint32_t)ch * 20480;
#pragma unroll
        for (int p = 0; p < 2; p++) {
            const uint32_t ro = (uint32_t)p * 5120;  // 64 rows * 80B
            const size_t go = ((size_t)p << 6) * Ec;
            if (CVTA) {
#pragma unroll
                for (int u = 0; u < 4; u++)
                    pa[p][u] =
                        *(const float4*)(Apf + go + (ch << 5) + (u << 2));
                STS128(dstA + st + ro, h2(pa[p][0].x, pa[p][0].y),
                       h2(pa[p][0].z, pa[p][0].w), h2(pa[p][1].x, pa[p][1].y),
                       h2(pa[p][1].z, pa[p][1].w));
                STS128(dstA + st + ro + 16, h2(pa[p][2].x, pa[p][2].y),
                       h2(pa[p][2].z, pa[p][2].w), h2(pa[p][3].x, pa[p][3].y),
                       h2(pa[p][3].z, pa[p][3].w));
            } else {
                cp16(dstA + st + ro, Aph + go + (ch << 5));
                cp16(dstA + st + ro + 16, Aph + go + (ch << 5) + 8);
            }
            cp16(dstW + st + ro, Wp + go + (ch << 5));
            cp16(dstW + st + ro + 16, Wp + go + (ch << 5) + 8);
        }
        CP_COMMIT;
    }
    if (CVTA) {  // prefetch chunk 2
#pragma unroll
        for (int p = 0; p < 2; p++)
#pragma unroll
            for (int u = 0; u < 4; u++)
                pa[p][u] = *(const float4*)(Apf + (((size_t)p << 6) * Ec) +
                                            (2 << 5) + (u << 2));
    }

    for (int c = 0; c < 32; c++) {
        if (c < 31) { CP_WAIT(1); } else { CP_WAIT(0); }
        __syncthreads();  // chunk c visible; chunk c-1 readers done

        // stage chunk c+2 into slot (c+2)%3 (== (c-1)%3, readers passed sync)
        if (c + 2 < 32) {
            const uint32_t st = (uint32_t)((c + 2) % 3) * 20480;
            const int nch = c + 2;
#pragma unroll
            for (int p = 0; p < 2; p++) {
                const uint32_t ro = (uint32_t)p * 5120;
                const size_t go = ((size_t)p << 6) * Ec;
                if (CVTA) {  // pa holds chunk c+2
                    STS128(dstA + st + ro, h2(pa[p][0].x, pa[p][0].y),
                           h2(pa[p][0].z, pa[p][0].w),
                           h2(pa[p][1].x, pa[p][1].y),
                           h2(pa[p][1].z, pa[p][1].w));
                    STS128(dstA + st + ro + 16, h2(pa[p][2].x, pa[p][2].y),
                           h2(pa[p][2].z, pa[p][2].w),
                           h2(pa[p][3].x, pa[p][3].y),
                           h2(pa[p][3].z, pa[p][3].w));
                } else {
                    cp16(dstA + st + ro, Aph + go + (nch << 5));
                    cp16(dstA + st + ro + 16, Aph + go + (nch << 5) + 8);
                }
                cp16(dstW + st + ro, Wp + go + (nch << 5));
                cp16(dstW + st + ro + 16, Wp + go + (nch << 5) + 8);
            }
            CP_COMMIT;
            if (CVTA && c + 3 < 32) {
#pragma unroll
                for (int p = 0; p < 2; p++)
#pragma unroll
                    for (int u = 0; u < 4; u++)
                        pa[p][u] =
                            *(const float4*)(Apf + (((size_t)p << 6) * Ec) +
                                             ((c + 3) << 5) + (u << 2));
            }
        }

        const uint32_t asb = smb + (uint32_t)(c % 3) * 20480;
        const uint32_t wsb = asb + 10240;
#pragma unroll
        for (int ki = 0; ki < 2; ki++) {
            uint32_t af[4][4];
#pragma unroll
            for (int mi = 0; mi < 4; mi++)
                ldsm4(af[mi], asb + a_lane + mi * 1280 + ki * 32);
#pragma unroll
            for (int t = 0; t < 4; t++) {
                uint32_t bq[4];
                ldsm4(bq, wsb + b_lane + t * 1280 + ki * 32);
#pragma unroll
                for (int mi = 0; mi < 4; mi++) {
                    mma16(acc[mi][2 * t], af[mi], bq);
                    mma16(acc[mi][2 * t + 1], af[mi], bq + 2);
                }
            }
        }
    }

    // Epilogue
#pragma unroll
    for (int ni = 0; ni < 8; ni++) {
        const int col = c0 + (wn << 6) + (ni << 3) + (gc << 1);
        const float2 b2 = *(const float2*)&bias[col];
#pragma unroll
        for (int mi = 0; mi < 4; mi++) {
            const int row = r0 + (wm << 6) + (mi << 4) + gr;
            float v00 = acc[mi][ni][0] + b2.x, v01 = acc[mi][ni][1] + b2.y;
            float v10 = acc[mi][ni][2] + b2.x, v11 = acc[mi][ni][3] + b2.y;
            if (EPI == 0) {
                float* C = (float*)Cv;
                *(float2*)&C[(size_t)row * Ec + col] = make_float2(v00, v01);
                *(float2*)&C[(size_t)(row + 8) * Ec + col] =
                    make_float2(v10, v11);
            } else {
                if (EPI == 1) {
                    v00 *= 0.125f; v01 *= 0.125f; v10 *= 0.125f; v11 *= 0.125f;
                }
                const int b = row >> 11, s = row & (Sc - 1);
                const int h = col >> 6, d = col & (HDc - 1);
                const int bh = (b << 4) + h;
                __half* C = (__half*)Cv;
                if (EPI == 3) {
                    // [bh][d][s]
                    __half* base0 = C + (((size_t)(bh << 6) + d) << 11) + s;
                    __half* base1 = base0 + Sc;  // d+1
                    base0[0] = __float2half_rn(v00);
                    base0[8] = __float2half_rn(v10);
                    base1[0] = __float2half_rn(v01);
                    base1[8] = __float2half_rn(v11);
                } else {
                    // [bh][s][d]
                    __half* base = C + ((size_t)bh << 17) + (s << 6) + d;
                    *(uint32_t*)base = h2(v00, v01);
                    *(uint32_t*)(base + (8 << 6)) = h2(v10, v11);
                }
            }
        }
    }
}

// ---------------------------------------------------------------------------
// Flash attention (byte-identical to R13): fp16 mma, fp32 softmax/acc.
// THREE-stage KV ring, one sync per tile.
// SMEM bytes: KV slots [0,18432) [18432,36864) [36864,55296),
//             Ps/Qstage [55296,73728). Rows: 64 halves + 16B pad = 144B.
// ---------------------------------------------------------------------------
__global__ void __launch_bounds__(256, 2)
    attn_tc(const __half* __restrict__ Q, const __half* __restrict__ K,
            const __half* __restrict__ V, __half* __restrict__ O) {
    extern __shared__ uint32_t asm_sm[];
    const uint32_t smb = (uint32_t)__cvta_generic_to_shared(asm_sm);
    const uint32_t PsB = smb + 55296;
    char* PsG = (char*)asm_sm + 55296;

    const int tid = threadIdx.x, lane = tid & 31, warp = tid >> 5;
    const int gr = lane >> 2, gc = lane & 3;
    const int qi = gridDim.x - 1 - blockIdx.x;  // heavy tiles first
    const int bh = blockIdx.y;
    const int q0 = qi << 7;
    const int rb = warp << 4;

    const int lm15 = lane & 15, l7 = lane & 7, l16 = (lane >> 4) & 1;
    const uint32_t colA = ((lane >> 4) & 1) << 4;
    const uint32_t colB = ((lane >> 3) & 1) << 4;
    const uint32_t p_lane = (uint32_t)(rb + lm15) * 144 + colA;
    const uint32_t kb_lane = (uint32_t)(l16 * 8 + l7) * 144 + colB;

    const __half* qb = Q + ((size_t)bh << 17);
    const __half* kb = K + ((size_t)bh << 17);
    const __half* vb = V + ((size_t)bh << 17);

    const int krow = tid >> 2, ku = (tid & 3) * 2;
    auto stage_kv = [&](int kt, uint32_t slot) {
        const int t0 = kt << 6;
        const uint32_t st = slot * 18432;
#pragma unroll
        for (int u = 0; u < 2; u++) {
            cp16(smb + st + (uint32_t)krow * 144 + (ku + u) * 16,
                 kb + (size_t)(t0 + krow) * HDc + (ku + u) * 8);
            cp16(smb + st + 9216 + (uint32_t)krow * 144 + (ku + u) * 16,
                 vb + (size_t)krow * Sc + t0 + (ku + u) * 8);
        }
        CP_COMMIT;
    };

    const int ktiles = (qi << 1) + 2;

    stage_kv(0, 0);
    const int qrow = tid >> 1, qseg = (tid & 1) * 4;
#pragma unroll
    for (int u = 0; u < 4; u++)
        cp16(PsB + (uint32_t)qrow * 144 + (qseg + u) * 16,
             qb + (size_t)(q0 + qrow) * HDc + (qseg + u) * 8);
    CP_COMMIT;
    CP_WAIT(0);
    __syncthreads();
    uint32_t qf[4][4];
#pragma unroll
    for (int ki = 0; ki < 4; ki++) ldsm4(qf[ki], PsB + p_lane + ki * 32);
    __syncthreads();
    if (ktiles > 1) stage_kv(1, 1);

    float m0 = -1e30f, m1 = -1e30f, l0 = 0.f, l1 = 0.f;
    float o[8][4];
#pragma unroll
    for (int ni = 0; ni < 8; ni++)
#pragma unroll
        for (int j = 0; j < 4; j++) o[ni][j] = 0.f;

    for (int kt = 0; kt < ktiles; kt++) {
        if (kt + 1 < ktiles) { CP_WAIT(1); } else { CP_WAIT(0); }
        __syncthreads();

        if (kt + 2 < ktiles) stage_kv(kt + 2, (uint32_t)((kt + 2) % 3));

        const uint32_t ksb = smb + (uint32_t)(kt % 3) * 18432;
        const uint32_t vsb = ksb + 9216;

        float s[8][4];
#pragma unroll
        for (int ni = 0; ni < 8; ni++)
#pragma unroll
            for (int j = 0; j < 4; j++) s[ni][j] = 0.f;
#pragma unroll
        for (int ki = 0; ki < 4; ki++) {
#pragma unroll
            for (int t = 0; t < 4; t++) {
                uint32_t bq[4];
                ldsm4(bq, ksb + kb_lane + t * 2304 + ki * 32);
                mma16(s[2 * t], qf[ki], bq);
                mma16(s[2 * t + 1], qf[ki], bq + 2);
            }
        }

        const int k0 = kt << 6;
        if (k0 + 63 > q0) {
            const int row0 = q0 + rb + gr, row1 = row0 + 8;
#pragma unroll
            for (int ni = 0; ni < 8; ni++) {
                const int cg = k0 + (ni << 3) + (gc << 1);
                if (cg > row0) s[ni][0] = -1e30f;
                if (cg + 1 > row0) s[ni][1] = -1e30f;
                if (cg > row1) s[ni][2] = -1e30f;
                if (cg + 1 > row1) s[ni][3] = -1e30f;
            }
        }

        float mx0 = -1e30f, mx1 = -1e30f;
#pragma unroll
        for (int ni = 0; ni < 8; ni++) {
            mx0 = fmaxf(mx0, fmaxf(s[ni][0], s[ni][1]));
            mx1 = fmaxf(mx1, fmaxf(s[ni][2], s[ni][3]));
        }
        mx0 = fmaxf(mx0, __shfl_xor_sync(0xffffffffu, mx0, 1));
        mx0 = fmaxf(mx0, __shfl_xor_sync(0xffffffffu, mx0, 2));
        mx1 = fmaxf(mx1, __shfl_xor_sync(0xffffffffu, mx1, 1));
        mx1 = fmaxf(mx1, __shfl_xor_sync(0xffffffffu, mx1, 2));

        const float mn0 = fmaxf(m0, mx0), mn1 = fmaxf(m1, mx1);
        const float cor0 = __expf(m0 - mn0), cor1 = __expf(m1 - mn1);
        float sum0 = 0.f, sum1 = 0.f;
#pragma unroll
        for (int ni = 0; ni < 8; ni++) {
            s[ni][0] = __expf(s[ni][0] - mn0);
            s[ni][1] = __expf(s[ni][1] - mn0);
            s[ni][2] = __expf(s[ni][2] - mn1);
            s[ni][3] = __expf(s[ni][3] - mn1);
            sum0 += s[ni][0] + s[ni][1];
            sum1 += s[ni][2] + s[ni][3];
        }
        sum0 += __shfl_xor_sync(0xffffffffu, sum0, 1);
        sum0 += __shfl_xor_sync(0xffffffffu, sum0, 2);
        sum1 += __shfl_xor_sync(0xffffffffu, sum1, 1);
        sum1 += __shfl_xor_sync(0xffffffffu, sum1, 2);

        l0 = l0 * cor0 + sum0;
        l1 = l1 * cor1 + sum1;
        m0 = mn0;
        m1 = mn1;
#pragma unroll
        for (int ni = 0; ni < 8; ni++) {
            o[ni][0] *= cor0;
            o[ni][1] *= cor0;
            o[ni][2] *= cor1;
            o[ni][3] *= cor1;
        }

#pragma unroll
        for (int ni = 0; ni < 8; ni++) {
            char* a0 = PsG + (uint32_t)(rb + gr) * 144 +
                       ((ni << 3) + (gc << 1)) * 2;
            *(uint32_t*)a0 = h2(s[ni][0], s[ni][1]);
            *(uint32_t*)(a0 + 1152) = h2(s[ni][2], s[ni][3]);
        }
        __syncwarp();

#pragma unroll
        for (int ki = 0; ki < 4; ki++) {
            uint32_t pf[4];
            ldsm4(pf, PsB + p_lane + ki * 32);
#pragma unroll
            for (int t = 0; t < 4; t++) {
                uint32_t bq[4];
                ldsm4(bq, vsb + kb_lane + t * 2304 + ki * 32);
                mma16(o[2 * t], pf, bq);
                mma16(o[2 * t + 1], pf, bq + 2);
            }
        }
    }

    const int b = bh >> 4, h = bh & 15;
    const float i0 = 1.f / l0, i1 = 1.f / l1;
    __half* ob = O + ((size_t)b * Sc) * Ec + h * HDc;
    const int row0 = q0 + rb + gr;
#pragma unroll
    for (int ni = 0; ni < 8; ni++) {
        const int d = (ni << 3) + (gc << 1);
        *(uint32_t*)(ob + (size_t)row0 * Ec + d) =
            h2(o[ni][0] * i0, o[ni][1] * i0);
        *(uint32_t*)(ob + (size_t)(row0 + 8) * Ec + d) =
            h2(o[ni][2] * i1, o[ni][3] * i1);
    }
}

// ---------------------------------------------------------------------------
// Inputs: 0 values, 1 keys, 2 queries, 3 mask, 4 Wv, 5 bv, 6 Wk, 7 bk,
//         8 Wq, 9 bq, 10 Wo, 11 bo
// ---------------------------------------------------------------------------
extern "C" void kernel_launch(void* const* d_in, const int* in_sizes, int n_in,
                              void* d_out, int out_size) {
    const float* values = (const float*)d_in[0];
    const float* keys = (const float*)d_in[1];
    const float* queries = (const float*)d_in[2];
    const float* Wv = (const float*)d_in[4];
    const float* bv = (const float*)d_in[5];
    const float* Wk = (const float*)d_in[6];
    const float* bk = (const float*)d_in[7];
    const float* Wq = (const float*)d_in[8];
    const float* bq = (const float*)d_in[9];
    const float* Wo = (const float*)d_in[10];
    const float* bo = (const float*)d_in[11];
    float* out = (float*)d_out;

    __half *qb_, *kb_, *vb_, *ab_, *wq_, *wk_, *wv_, *wo_;
    cudaGetSymbolAddress((void**)&qb_, g_q);
    cudaGetSymbolAddress((void**)&kb_, g_k);
    cudaGetSymbolAddress((void**)&vb_, g_v);
    cudaGetSymbolAddress((void**)&ab_, g_attn);
    cudaGetSymbolAddress((void**)&wq_, g_wq);
    cudaGetSymbolAddress((void**)&wk_, g_wk);
    cudaGetSymbolAddress((void**)&wv_, g_wv);
    cudaGetSymbolAddress((void**)&wo_, g_wo);

    const int gemm_smem = 61440;  // 3 stages x 20480
    const int attn_smem = 73728;  // 3 KV slots + Ps
    cudaFuncSetAttribute(gemm_tc<0, 0>, cudaFuncAttributeMaxDynamicSharedMemorySize, gemm_smem);
    cudaFuncSetAttribute(gemm_tc<1, 1>, cudaFuncAttributeMaxDynamicSharedMemorySize, gemm_smem);
    cudaFuncSetAttribute(gemm_tc<2, 1>, cudaFuncAttributeMaxDynamicSharedMemorySize, gemm_smem);
    cudaFuncSetAttribute(gemm_tc<3, 1>, cudaFuncAttributeMaxDynamicSharedMemorySize, gemm_smem);
    cudaFuncSetAttribute(attn_tc, cudaFuncAttributeMaxDynamicSharedMemorySize, attn_smem);

    dim3 gw(256, 4);
    conv_w<<<gw, 256>>>((const float4*)Wq, (uint2*)wq_, (const float4*)Wk,
                        (uint2*)wk_, (const float4*)Wv, (uint2*)wv_,
                        (const float4*)Wo, (uint2*)wo_);

    dim3 gg(Mrows / 128, Ec / 128);  // (64, 8)
    gemm_tc<1, 1><<<gg, 128, gemm_smem>>>(queries, wq_, bq, qb_);
    gemm_tc<2, 1><<<gg, 128, gemm_smem>>>(keys, wk_, bk, kb_);
    gemm_tc<3, 1><<<gg, 128, gemm_smem>>>(values, wv_, bv, vb_);

    dim3 ga(Sc / 128, 4 * Hc);  // (16, 64)
    attn_tc<<<ga, 256, attn_smem>>>(qb_, kb_, vb_, ab_);

    gemm_tc<0, 0><<<gg, 128, gemm_smem>>>(ab_, wo_, bo, out);
}

// round 16
// speedup vs baseline: 1.1685x; 1.0160x over previous
#include <cuda_runtime.h>
#include <cuda_fp16.h>
#include <cstdint>

#define Sc 2048
#define Ec 1024
#define Hc 16
#define HDc 64
#define Mrows 8192

// Scratch (fp16). q/k: [bh][s][d]; v: [bh][d][s]; attn: [b][s][e]
__device__ __half g_q[(size_t)Mrows * Ec];
__device__ __half g_k[(size_t)Mrows * Ec];
__device__ __half g_v[(size_t)Mrows * Ec];
__device__ __half g_attn[(size_t)Mrows * Ec];
// fp16 pre-converted weights
__device__ __half g_wq[(size_t)Ec * Ec];
__device__ __half g_wk[(size_t)Ec * Ec];
__device__ __half g_wv[(size_t)Ec * Ec];
__device__ __half g_wo[(size_t)Ec * Ec];

__device__ __forceinline__ uint32_t h2(float x, float y) {
    __half2 h = __halves2half2(__float2half_rn(x), __float2half_rn(y));
    return *reinterpret_cast<uint32_t*>(&h);
}

__device__ __forceinline__ void mma16(float c[4], const uint32_t a[4],
                                      const uint32_t b[2]) {
    asm volatile(
        "mma.sync.aligned.m16n8k16.row.col.f32.f16.f16.f32 "
        "{%0,%1,%2,%3}, {%4,%5,%6,%7}, {%8,%9}, {%0,%1,%2,%3};\n"
        : "+f"(c[0]), "+f"(c[1]), "+f"(c[2]), "+f"(c[3])
        : "r"(a[0]), "r"(a[1]), "r"(a[2]), "r"(a[3]), "r"(b[0]), "r"(b[1]));
}

__device__ __forceinline__ void ldsm4(uint32_t r[4], uint32_t a) {
    asm volatile(
        "ldmatrix.sync.aligned.m8n8.x4.shared.b16 {%0,%1,%2,%3}, [%4];"
        : "=r"(r[0]), "=r"(r[1]), "=r"(r[2]), "=r"(r[3])
        : "r"(a));
}

__device__ __forceinline__ void cp16(uint32_t s, const void* g) {
    asm volatile("cp.async.cg.shared.global [%0], [%1], 16;" ::"r"(s), "l"(g)
                 : "memory");
}
#define CP_COMMIT asm volatile("cp.async.commit_group;" ::: "memory")
#define CP_WAIT(n) asm volatile("cp.async.wait_group %0;" ::"n"(n) : "memory")
#define STS128(a, u0, u1, u2, u3)                                  \
    asm volatile("st.shared.v4.b32 [%0], {%1,%2,%3,%4};" ::"r"(a), \
                 "r"(u0), "r"(u1), "r"(u2), "r"(u3))

// ---------------------------------------------------------------------------
// fp16 pre-convert for the 4 weight matrices in one launch
// ---------------------------------------------------------------------------
__global__ void conv_w(const float4* __restrict__ s0, uint2* __restrict__ d0,
                       const float4* __restrict__ s1, uint2* __restrict__ d1,
                       const float4* __restrict__ s2, uint2* __restrict__ d2,
                       const float4* __restrict__ s3, uint2* __restrict__ d3) {
    const float4* src;
    uint2* dst;
    switch (blockIdx.y) {
        case 0: src = s0; dst = d0; break;
        case 1: src = s1; dst = d1; break;
        case 2: src = s2; dst = d2; break;
        default: src = s3; dst = d3; break;
    }
    const int n4 = Ec * Ec / 4;
    int i = blockIdx.x * blockDim.x + threadIdx.x;
    const int stride = gridDim.x * blockDim.x;
    for (; i < n4; i += stride) {
        float4 v = src[i];
        dst[i] = make_uint2(h2(v.x, v.y), h2(v.z, v.w));
    }
}

// ---------------------------------------------------------------------------
// fp16 GEMM (byte-identical to R15): C[M,1024] = A @ W^T + bias.
// CTA = 128 threads (4 warps), tile 128x128, warp tile 64x64 (2m x 2n).
// BK=32 (32 chunks), 3-stage ring, stage-ahead 2, one sync per chunk.
// SMEM row = 32 halves (64B) + 16B pad = 80B; stage A+W = 20480B; x3 = 61440B.
// CVTA=1: A raw fp32, 2-pass register-prefetched LDG->cvt->STS staging.
// EPI: 0 fp32 [M,N]; 1 Q (x0.125, fp16, [bh][s][d]); 2 K (fp16, [bh][s][d]);
//      3 V (fp16, transposed [bh][d][s]).
// ---------------------------------------------------------------------------
template <int EPI, int CVTA>
__global__ void __launch_bounds__(128, 2)
    gemm_tc(const void* __restrict__ Av, const __half* __restrict__ W,
            const float* __restrict__ bias, void* __restrict__ Cv) {
    extern __shared__ uint32_t gsm[];
    const uint32_t smb = (uint32_t)__cvta_generic_to_shared(gsm);

    const int tid = threadIdx.x, lane = tid & 31, warp = tid >> 5;
    const int wm = warp >> 1, wn = warp & 1;  // 2(m) x 2(n), 64x64 each
    const int gr = lane >> 2, gc = lane & 3;
    const int r0 = blockIdx.x << 7, c0 = blockIdx.y << 7;

    const int lm15 = lane & 15, l7 = lane & 7, l16 = (lane >> 4) & 1;
    const uint32_t colA = ((lane >> 4) & 1) << 4;
    const uint32_t colB = ((lane >> 3) & 1) << 4;
    const uint32_t a_lane = (uint32_t)(wm * 64 + lm15) * 80 + colA;
    const uint32_t b_lane = (uint32_t)(wn * 64 + l16 * 8 + l7) * 80 + colB;

    // staging: 2 threads per row (64 rows/pass), 32B each, 2 passes
    const int srow = tid >> 1, sseg = (tid & 1) << 4;
    const uint32_t dstA = smb + (uint32_t)srow * 80 + sseg * 2;
    const uint32_t dstW = dstA + 10240;
    const float* Apf = (const float*)Av + (size_t)(r0 + srow) * Ec + sseg;
    const __half* Aph = (const __half*)Av + (size_t)(r0 + srow) * Ec + sseg;
    const __half* Wp = W + (size_t)(c0 + srow) * Ec + sseg;

    float acc[4][8][4];
#pragma unroll
    for (int mi = 0; mi < 4; mi++)
#pragma unroll
        for (int ni = 0; ni < 8; ni++)
#pragma unroll
            for (int j = 0; j < 4; j++) acc[mi][ni][j] = 0.f;

    float4 pa[2][4];
    // prologue: stage chunks 0,1 into slots 0,1
#pragma unroll
    for (int ch = 0; ch < 2; ch++) {
        const uint32_t st = (uint32_t)ch * 20480;
#pragma unroll
        for (int p = 0; p < 2; p++) {
            const uint32_t ro = (uint32_t)p * 5120;  // 64 rows * 80B
            const size_t go = ((size_t)p << 6) * Ec;
            if (CVTA) {
#pragma unroll
                for (int u = 0; u < 4; u++)
                    pa[p][u] =
                        *(const float4*)(Apf + go + (ch << 5) + (u << 2));
                STS128(dstA + st + ro, h2(pa[p][0].x, pa[p][0].y),
                       h2(pa[p][0].z, pa[p][0].w), h2(pa[p][1].x, pa[p][1].y),
                       h2(pa[p][1].z, pa[p][1].w));
                STS128(dstA + st + ro + 16, h2(pa[p][2].x, pa[p][2].y),
                       h2(pa[p][2].z, pa[p][2].w), h2(pa[p][3].x, pa[p][3].y),
                       h2(pa[p][3].z, pa[p][3].w));
            } else {
                cp16(dstA + st + ro, Aph + go + (ch << 5));
                cp16(dstA + st + ro + 16, Aph + go + (ch << 5) + 8);
            }
            cp16(dstW + st + ro, Wp + go + (ch << 5));
            cp16(dstW + st + ro + 16, Wp + go + (ch << 5) + 8);
        }
        CP_COMMIT;
    }
    if (CVTA) {  // prefetch chunk 2
#pragma unroll
        for (int p = 0; p < 2; p++)
#pragma unroll
            for (int u = 0; u < 4; u++)
                pa[p][u] = *(const float4*)(Apf + (((size_t)p << 6) * Ec) +
                                            (2 << 5) + (u << 2));
    }

    for (int c = 0; c < 32; c++) {
        if (c < 31) { CP_WAIT(1); } else { CP_WAIT(0); }
        __syncthreads();  // chunk c visible; chunk c-1 readers done

        if (c + 2 < 32) {
            const uint32_t st = (uint32_t)((c + 2) % 3) * 20480;
            const int nch = c + 2;
#pragma unroll
            for (int p = 0; p < 2; p++) {
                const uint32_t ro = (uint32_t)p * 5120;
                const size_t go = ((size_t)p << 6) * Ec;
                if (CVTA) {  // pa holds chunk c+2
                    STS128(dstA + st + ro, h2(pa[p][0].x, pa[p][0].y),
                           h2(pa[p][0].z, pa[p][0].w),
                           h2(pa[p][1].x, pa[p][1].y),
                           h2(pa[p][1].z, pa[p][1].w));
                    STS128(dstA + st + ro + 16, h2(pa[p][2].x, pa[p][2].y),
                           h2(pa[p][2].z, pa[p][2].w),
                           h2(pa[p][3].x, pa[p][3].y),
                           h2(pa[p][3].z, pa[p][3].w));
                } else {
                    cp16(dstA + st + ro, Aph + go + (nch << 5));
                    cp16(dstA + st + ro + 16, Aph + go + (nch << 5) + 8);
                }
                cp16(dstW + st + ro, Wp + go + (nch << 5));
                cp16(dstW + st + ro + 16, Wp + go + (nch << 5) + 8);
            }
            CP_COMMIT;
            if (CVTA && c + 3 < 32) {
#pragma unroll
                for (int p = 0; p < 2; p++)
#pragma unroll
                    for (int u = 0; u < 4; u++)
                        pa[p][u] =
                            *(const float4*)(Apf + (((size_t)p << 6) * Ec) +
                                             ((c + 3) << 5) + (u << 2));
            }
        }

        const uint32_t asb = smb + (uint32_t)(c % 3) * 20480;
        const uint32_t wsb = asb + 10240;
#pragma unroll
        for (int ki = 0; ki < 2; ki++) {
            uint32_t af[4][4];
#pragma unroll
            for (int mi = 0; mi < 4; mi++)
                ldsm4(af[mi], asb + a_lane + mi * 1280 + ki * 32);
#pragma unroll
            for (int t = 0; t < 4; t++) {
                uint32_t bq[4];
                ldsm4(bq, wsb + b_lane + t * 1280 + ki * 32);
#pragma unroll
                for (int mi = 0; mi < 4; mi++) {
                    mma16(acc[mi][2 * t], af[mi], bq);
                    mma16(acc[mi][2 * t + 1], af[mi], bq + 2);
                }
            }
        }
    }

    // Epilogue
#pragma unroll
    for (int ni = 0; ni < 8; ni++) {
        const int col = c0 + (wn << 6) + (ni << 3) + (gc << 1);
        const float2 b2 = *(const float2*)&bias[col];
#pragma unroll
        for (int mi = 0; mi < 4; mi++) {
            const int row = r0 + (wm << 6) + (mi << 4) + gr;
            float v00 = acc[mi][ni][0] + b2.x, v01 = acc[mi][ni][1] + b2.y;
            float v10 = acc[mi][ni][2] + b2.x, v11 = acc[mi][ni][3] + b2.y;
            if (EPI == 0) {
                float* C = (float*)Cv;
                *(float2*)&C[(size_t)row * Ec + col] = make_float2(v00, v01);
                *(float2*)&C[(size_t)(row + 8) * Ec + col] =
                    make_float2(v10, v11);
            } else {
                if (EPI == 1) {
                    v00 *= 0.125f; v01 *= 0.125f; v10 *= 0.125f; v11 *= 0.125f;
                }
                const int b = row >> 11, s = row & (Sc - 1);
                const int h = col >> 6, d = col & (HDc - 1);
                const int bh = (b << 4) + h;
                __half* C = (__half*)Cv;
                if (EPI == 3) {
                    // [bh][d][s]
                    __half* base0 = C + (((size_t)(bh << 6) + d) << 11) + s;
                    __half* base1 = base0 + Sc;  // d+1
                    base0[0] = __float2half_rn(v00);
                    base0[8] = __float2half_rn(v10);
                    base1[0] = __float2half_rn(v01);
                    base1[8] = __float2half_rn(v11);
                } else {
                    // [bh][s][d]
                    __half* base = C + ((size_t)bh << 17) + (s << 6) + d;
                    *(uint32_t*)base = h2(v00, v01);
                    *(uint32_t*)(base + (8 << 6)) = h2(v10, v11);
                }
            }
        }
    }
}

// ---------------------------------------------------------------------------
// Flash attention: fp16 mma, fp32 softmax/acc. THREE-stage KV ring, one sync
// per tile. P tile NEVER touches SMEM: the m16n8 C-fragment maps exactly onto
// the m16n8k16 A-fragment, so pf is packed directly from s[] registers with
// the same h2 rounding the old store+ldmatrix path applied (bit-identical).
// SMEM bytes: KV slots [0,18432) [18432,36864) [36864,55296),
//             Q stage [55296,73728). Rows: 64 halves + 16B pad = 144B.
// ---------------------------------------------------------------------------
__global__ void __launch_bounds__(256, 2)
    attn_tc(const __half* __restrict__ Q, const __half* __restrict__ K,
            const __half* __restrict__ V, __half* __restrict__ O) {
    extern __shared__ uint32_t asm_sm[];
    const uint32_t smb = (uint32_t)__cvta_generic_to_shared(asm_sm);
    const uint32_t PsB = smb + 55296;

    const int tid = threadIdx.x, lane = tid & 31, warp = tid >> 5;
    const int gr = lane >> 2, gc = lane & 3;
    const int qi = gridDim.x - 1 - blockIdx.x;  // heavy tiles first
    const int bh = blockIdx.y;
    const int q0 = qi << 7;
    const int rb = warp << 4;

    const int lm15 = lane & 15, l7 = lane & 7, l16 = (lane >> 4) & 1;
    const uint32_t colA = ((lane >> 4) & 1) << 4;
    const uint32_t colB = ((lane >> 3) & 1) << 4;
    const uint32_t p_lane = (uint32_t)(rb + lm15) * 144 + colA;
    const uint32_t kb_lane = (uint32_t)(l16 * 8 + l7) * 144 + colB;

    const __half* qb = Q + ((size_t)bh << 17);
    const __half* kb = K + ((size_t)bh << 17);
    const __half* vb = V + ((size_t)bh << 17);

    const int krow = tid >> 2, ku = (tid & 3) * 2;
    auto stage_kv = [&](int kt, uint32_t slot) {
        const int t0 = kt << 6;
        const uint32_t st = slot * 18432;
#pragma unroll
        for (int u = 0; u < 2; u++) {
            cp16(smb + st + (uint32_t)krow * 144 + (ku + u) * 16,
                 kb + (size_t)(t0 + krow) * HDc + (ku + u) * 8);
            cp16(smb + st + 9216 + (uint32_t)krow * 144 + (ku + u) * 16,
                 vb + (size_t)krow * Sc + t0 + (ku + u) * 8);
        }
        CP_COMMIT;
    };

    const int ktiles = (qi << 1) + 2;

    stage_kv(0, 0);
    const int qrow = tid >> 1, qseg = (tid & 1) * 4;
#pragma unroll
    for (int u = 0; u < 4; u++)
        cp16(PsB + (uint32_t)qrow * 144 + (qseg + u) * 16,
             qb + (size_t)(q0 + qrow) * HDc + (qseg + u) * 8);
    CP_COMMIT;
    CP_WAIT(0);
    __syncthreads();
    uint32_t qf[4][4];
#pragma unroll
    for (int ki = 0; ki < 4; ki++) ldsm4(qf[ki], PsB + p_lane + ki * 32);
    if (ktiles > 1) stage_kv(1, 1);

    float m0 = -1e30f, m1 = -1e30f, l0 = 0.f, l1 = 0.f;
    float o[8][4];
#pragma unroll
    for (int ni = 0; ni < 8; ni++)
#pragma unroll
        for (int j = 0; j < 4; j++) o[ni][j] = 0.f;

    for (int kt = 0; kt < ktiles; kt++) {
        if (kt + 1 < ktiles) { CP_WAIT(1); } else { CP_WAIT(0); }
        __syncthreads();  // tile kt visible; tile kt-1 readers done

        if (kt + 2 < ktiles) stage_kv(kt + 2, (uint32_t)((kt + 2) % 3));

        const uint32_t ksb = smb + (uint32_t)(kt % 3) * 18432;
        const uint32_t vsb = ksb + 9216;

        // S = Q @ K^T
        float s[8][4];
#pragma unroll
        for (int ni = 0; ni < 8; ni++)
#pragma unroll
            for (int j = 0; j < 4; j++) s[ni][j] = 0.f;
#pragma unroll
        for (int ki = 0; ki < 4; ki++) {
#pragma unroll
            for (int t = 0; t < 4; t++) {
                uint32_t bq[4];
                ldsm4(bq, ksb + kb_lane + t * 2304 + ki * 32);
                mma16(s[2 * t], qf[ki], bq);
                mma16(s[2 * t + 1], qf[ki], bq + 2);
            }
        }

        // causal mask on diagonal-overlapping tiles
        const int k0 = kt << 6;
        if (k0 + 63 > q0) {
            const int row0 = q0 + rb + gr, row1 = row0 + 8;
#pragma unroll
            for (int ni = 0; ni < 8; ni++) {
                const int cg = k0 + (ni << 3) + (gc << 1);
                if (cg > row0) s[ni][0] = -1e30f;
                if (cg + 1 > row0) s[ni][1] = -1e30f;
                if (cg > row1) s[ni][2] = -1e30f;
                if (cg + 1 > row1) s[ni][3] = -1e30f;
            }
        }

        // online softmax (fp32)
        float mx0 = -1e30f, mx1 = -1e30f;
#pragma unroll
        for (int ni = 0; ni < 8; ni++) {
            mx0 = fmaxf(mx0, fmaxf(s[ni][0], s[ni][1]));
            mx1 = fmaxf(mx1, fmaxf(s[ni][2], s[ni][3]));
        }
        mx0 = fmaxf(mx0, __shfl_xor_sync(0xffffffffu, mx0, 1));
        mx0 = fmaxf(mx0, __shfl_xor_sync(0xffffffffu, mx0, 2));
        mx1 = fmaxf(mx1, __shfl_xor_sync(0xffffffffu, mx1, 1));
        mx1 = fmaxf(mx1, __shfl_xor_sync(0xffffffffu, mx1, 2));

        const float mn0 = fmaxf(m0, mx0), mn1 = fmaxf(m1, mx1);
        const float cor0 = __expf(m0 - mn0), cor1 = __expf(m1 - mn1);
        float sum0 = 0.f, sum1 = 0.f;
#pragma unroll
        for (int ni = 0; ni < 8; ni++) {
            s[ni][0] = __expf(s[ni][0] - mn0);
            s[ni][1] = __expf(s[ni][1] - mn0);
            s[ni][2] = __expf(s[ni][2] - mn1);
            s[ni][3] = __expf(s[ni][3] - mn1);
            sum0 += s[ni][0] + s[ni][1];
            sum1 += s[ni][2] + s[ni][3];
        }
        sum0 += __shfl_xor_sync(0xffffffffu, sum0, 1);
        sum0 += __shfl_xor_sync(0xffffffffu, sum0, 2);
        sum1 += __shfl_xor_sync(0xffffffffu, sum1, 1);
        sum1 += __shfl_xor_sync(0xffffffffu, sum1, 2);

        l0 = l0 * cor0 + sum0;
        l1 = l1 * cor1 + sum1;
        m0 = mn0;
        m1 = mn1;
#pragma unroll
        for (int ni = 0; ni < 8; ni++) {
            o[ni][0] *= cor0;
            o[ni][1] *= cor0;
            o[ni][2] *= cor1;
            o[ni][3] *= cor1;
        }

        // O += P @ V, P fragments packed directly from s[] (bit-identical to
        // the old SMEM round-trip: same h2 rounding, same fragment mapping)
#pragma unroll
        for (int ki = 0; ki < 4; ki++) {
            uint32_t pf[4];
            pf[0] = h2(s[2 * ki][0], s[2 * ki][1]);
            pf[1] = h2(s[2 * ki][2], s[2 * ki][3]);
            pf[2] = h2(s[2 * ki + 1][0], s[2 * ki + 1][1]);
            pf[3] = h2(s[2 * ki + 1][2], s[2 * ki + 1][3]);
#pragma unroll
            for (int t = 0; t < 4; t++) {
                uint32_t bq[4];
                ldsm4(bq, vsb + kb_lane + t * 2304 + ki * 32);
                mma16(o[2 * t], pf, bq);
                mma16(o[2 * t + 1], pf, bq + 2);
            }
        }
    }

    // epilogue: normalize, fp16, write [b][s][e]
    const int b = bh >> 4, h = bh & 15;
    const float i0 = 1.f / l0, i1 = 1.f / l1;
    __half* ob = O + ((size_t)b * Sc) * Ec + h * HDc;
    const int row0 = q0 + rb + gr;
#pragma unroll
    for (int ni = 0; ni < 8; ni++) {
        const int d = (ni << 3) + (gc << 1);
        *(uint32_t*)(ob + (size_t)row0 * Ec + d) =
            h2(o[ni][0] * i0, o[ni][1] * i0);
        *(uint32_t*)(ob + (size_t)(row0 + 8) * Ec + d) =
            h2(o[ni][2] * i1, o[ni][3] * i1);
    }
}

// ---------------------------------------------------------------------------
// Inputs: 0 values, 1 keys, 2 queries, 3 mask, 4 Wv, 5 bv, 6 Wk, 7 bk,
//         8 Wq, 9 bq, 10 Wo, 11 bo
// ---------------------------------------------------------------------------
extern "C" void kernel_launch(void* const* d_in, const int* in_sizes, int n_in,
                              void* d_out, int out_size) {
    const float* values = (const float*)d_in[0];
    const float* keys = (const float*)d_in[1];
    const float* queries = (const float*)d_in[2];
    const float* Wv = (const float*)d_in[4];
    const float* bv = (const float*)d_in[5];
    const float* Wk = (const float*)d_in[6];
    const float* bk = (const float*)d_in[7];
    const float* Wq = (const float*)d_in[8];
    const float* bq = (const float*)d_in[9];
    const float* Wo = (const float*)d_in[10];
    const float* bo = (const float*)d_in[11];
    float* out = (float*)d_out;

    __half *qb_, *kb_, *vb_, *ab_, *wq_, *wk_, *wv_, *wo_;
    cudaGetSymbolAddress((void**)&qb_, g_q);
    cudaGetSymbolAddress((void**)&kb_, g_k);
    cudaGetSymbolAddress((void**)&vb_, g_v);
    cudaGetSymbolAddress((void**)&ab_, g_attn);
    cudaGetSymbolAddress((void**)&wq_, g_wq);
    cudaGetSymbolAddress((void**)&wk_, g_wk);
    cudaGetSymbolAddress((void**)&wv_, g_wv);
    cudaGetSymbolAddress((void**)&wo_, g_wo);

    const int gemm_smem = 61440;  // 3 stages x 20480
    const int attn_smem = 73728;  // 3 KV slots + Q stage
    cudaFuncSetAttribute(gemm_tc<0, 0>, cudaFuncAttributeMaxDynamicSharedMemorySize, gemm_smem);
    cudaFuncSetAttribute(gemm_tc<1, 1>, cudaFuncAttributeMaxDynamicSharedMemorySize, gemm_smem);
    cudaFuncSetAttribute(gemm_tc<2, 1>, cudaFuncAttributeMaxDynamicSharedMemorySize, gemm_smem);
    cudaFuncSetAttribute(gemm_tc<3, 1>, cudaFuncAttributeMaxDynamicSharedMemorySize, gemm_smem);
    cudaFuncSetAttribute(attn_tc, cudaFuncAttributeMaxDynamicSharedMemorySize, attn_smem);

    dim3 gw(256, 4);
    conv_w<<<gw, 256>>>((const float4*)Wq, (uint2*)wq_, (const float4*)Wk,
                        (uint2*)wk_, (const float4*)Wv, (uint2*)wv_,
                        (const float4*)Wo, (uint2*)wo_);

    dim3 gg(Mrows / 128, Ec / 128);  // (64, 8)
    gemm_tc<1, 1><<<gg, 128, gemm_smem>>>(queries, wq_, bq, qb_);
    gemm_tc<2, 1><<<gg, 128, gemm_smem>>>(keys, wk_, bk, kb_);
    gemm_tc<3, 1><<<gg, 128, gemm_smem>>>(values, wv_, bv, vb_);

    dim3 ga(Sc / 128, 4 * Hc);  // (16, 64)
    attn_tc<<<ga, 256, attn_smem>>>(qb_, kb_, vb_, ab_);

    gemm_tc<0, 0><<<gg, 128, gemm_smem>>>(ab_, wo_, bo, out);
}